// round 1
// baseline (speedup 1.0000x reference)
#include <cuda_runtime.h>
#include <cuda_bf16.h>
#include <cstdint>

#define NN 100000
#define NE 1600000

// Static scratch (no allocations allowed)
__device__ float g_fA[(size_t)NN * 128];   // projected features f
__device__ float g_fB[(size_t)NN * 128];   // accumulator / next-layer input h
__device__ float g_el[NN * 4];
__device__ float g_er[NN * 4];
__device__ float g_s[NN * 4];

// ---------------------------------------------------------------------------
__global__ void zero_kernel(float* __restrict__ p, int n4) {
    int i = blockIdx.x * blockDim.x + threadIdx.x;
    if (i < n4) ((float4*)p)[i] = make_float4(0.f, 0.f, 0.f, 0.f);
}

// ---------------------------------------------------------------------------
// Tiled fp32 GEMM: F[N,COLS] = X[N,128] @ W[128,COLS].  K=128 fixed.
// BLOCK_ROWS=64, thread tile 4 rows x 8 cols. blockDim = 16*(COLS/8).
template <int COLS>
__global__ void gemm_kernel(const float* __restrict__ X, const float* __restrict__ W,
                            float* __restrict__ F, int nrows) {
    constexpr int K  = 128;
    constexpr int BR = 64;
    extern __shared__ float sm[];
    float (*Xs)[K + 1] = (float(*)[K + 1])sm;       // [BR][129]
    float* Ws = sm + BR * (K + 1);                  // [K][COLS]

    const int tid  = threadIdx.x;
    const int nth  = blockDim.x;
    const int row0 = blockIdx.x * BR;

    // load W (entire matrix) into smem
    for (int i = tid; i < K * COLS / 4; i += nth)
        ((float4*)Ws)[i] = ((const float4*)W)[i];

    // load X tile
    for (int i = tid; i < BR * K / 4; i += nth) {
        int r  = i / (K / 4);
        int k4 = i % (K / 4);
        float4 v = (row0 + r < nrows)
                 ? ((const float4*)(X + (size_t)(row0 + r) * K))[k4]
                 : make_float4(0.f, 0.f, 0.f, 0.f);
        Xs[r][k4 * 4 + 0] = v.x; Xs[r][k4 * 4 + 1] = v.y;
        Xs[r][k4 * 4 + 2] = v.z; Xs[r][k4 * 4 + 3] = v.w;
    }
    __syncthreads();

    const int rc = tid % (BR / 4);   // 0..15 row group
    const int cc = tid / (BR / 4);   // col group

    float acc[4][8];
#pragma unroll
    for (int i = 0; i < 4; i++)
#pragma unroll
        for (int j = 0; j < 8; j++) acc[i][j] = 0.f;

#pragma unroll 8
    for (int k = 0; k < K; k++) {
        float a[4];
#pragma unroll
        for (int i = 0; i < 4; i++) a[i] = Xs[rc * 4 + i][k];
        float4 b0 = *(const float4*)&Ws[k * COLS + cc * 8];
        float4 b1 = *(const float4*)&Ws[k * COLS + cc * 8 + 4];
        float b[8] = {b0.x, b0.y, b0.z, b0.w, b1.x, b1.y, b1.z, b1.w};
#pragma unroll
        for (int i = 0; i < 4; i++)
#pragma unroll
            for (int j = 0; j < 8; j++) acc[i][j] = fmaf(a[i], b[j], acc[i][j]);
    }

#pragma unroll
    for (int i = 0; i < 4; i++) {
        int row = row0 + rc * 4 + i;
        if (row < nrows) {
            float4 s0 = make_float4(acc[i][0], acc[i][1], acc[i][2], acc[i][3]);
            float4 s1 = make_float4(acc[i][4], acc[i][5], acc[i][6], acc[i][7]);
            *(float4*)(F + (size_t)row * COLS + cc * 8)     = s0;
            *(float4*)(F + (size_t)row * COLS + cc * 8 + 4) = s1;
        }
    }
}

// ---------------------------------------------------------------------------
// el[n,h] = sum_d f[n,h,d]*al[h,d]; er likewise.
template <int H, int D>
__global__ void attn_kernel(const float* __restrict__ F, const float* __restrict__ al,
                            const float* __restrict__ ar, float* __restrict__ el,
                            float* __restrict__ er, int n) {
    int i = blockIdx.x * blockDim.x + threadIdx.x;   // node*H + h
    if (i >= n * H) return;
    int node = i / H, h = i % H;
    const float* f = F + (size_t)node * H * D + h * D;
    float sl = 0.f, sr = 0.f;
#pragma unroll
    for (int d = 0; d < D; d += 4) {
        float4 fv = *(const float4*)(f + d);
        float4 av = *(const float4*)(al + h * D + d);
        float4 rv = *(const float4*)(ar + h * D + d);
        sl += fv.x * av.x + fv.y * av.y + fv.z * av.z + fv.w * av.w;
        sr += fv.x * rv.x + fv.y * rv.y + fv.z * rv.z + fv.w * rv.w;
    }
    el[i] = sl;
    er[i] = sr;
}

// ---------------------------------------------------------------------------
// One warp per edge: w = exp(leakyrelu(el[src]+er[dst])) per head (max-shift
// dropped: alpha = w/s is invariant, scores are O(1) so no overflow).
// accum[dst] += w*f[src] via vector red; s[dst] += w.
template <int H, int D>
__global__ void edge_kernel(const float* __restrict__ F, const float* __restrict__ el,
                            const float* __restrict__ er, const int* __restrict__ src,
                            const int* __restrict__ dst, float* __restrict__ accum,
                            float* __restrict__ s, int E) {
    constexpr int HD = H * D;
    int warp_id = (blockIdx.x * blockDim.x + threadIdx.x) >> 5;
    int lane    = threadIdx.x & 31;
    if (warp_id >= E) return;

    int sn = __ldg(src + warp_id);
    int dn = __ldg(dst + warp_id);

    float w = 0.f;
    if (lane < H) {
        float v = el[sn * H + lane] + er[dn * H + lane];
        v = v > 0.f ? v : 0.2f * v;
        w = __expf(v);
        asm volatile("red.global.add.f32 [%0], %1;"
                     :: "l"(s + dn * H + lane), "f"(w) : "memory");
    }
    int h = ((lane * 4) / D) % H;
    float wh = __shfl_sync(0xffffffffu, w, h);   // uniform: all lanes participate
    if (lane < HD / 4) {
        float4 fv = *(const float4*)(F + (size_t)sn * HD + lane * 4);
        float* ap = accum + (size_t)dn * HD + lane * 4;
        asm volatile("red.global.add.v4.f32 [%0], {%1,%2,%3,%4};"
                     :: "l"(ap), "f"(fv.x * wh), "f"(fv.y * wh),
                        "f"(fv.z * wh), "f"(fv.w * wh) : "memory");
    }
}

// ---------------------------------------------------------------------------
template <int H, int D, bool ELU>
__global__ void norm_kernel(const float* __restrict__ accum, const float* __restrict__ s,
                            const float* __restrict__ b, float* __restrict__ out, int n) {
    constexpr int HD = H * D;
    int i = blockIdx.x * blockDim.x + threadIdx.x;
    if (i >= n * HD) return;
    int c = i % HD;
    int node = i / HD;
    int h = c / D;
    float sv = s[node * H + h];
    float v = accum[i] / fmaxf(sv, 1e-9f) + b[c];
    if (ELU) v = v > 0.f ? v : expm1f(v);
    out[i] = v;
}

// ---------------------------------------------------------------------------
extern "C" void kernel_launch(void* const* d_in, const int* in_sizes, int n_in,
                              void* d_out, int out_size) {
    const float* x   = (const float*)d_in[0];
    const int*   src = (const int*)d_in[1];
    const int*   dst = (const int*)d_in[2];
    const float* W1  = (const float*)d_in[3];
    const float* al1 = (const float*)d_in[4];
    const float* ar1 = (const float*)d_in[5];
    const float* b1  = (const float*)d_in[6];
    const float* W2  = (const float*)d_in[7];
    const float* al2 = (const float*)d_in[8];
    const float* ar2 = (const float*)d_in[9];
    const float* b2  = (const float*)d_in[10];
    const float* W3  = (const float*)d_in[11];
    const float* al3 = (const float*)d_in[12];
    const float* ar3 = (const float*)d_in[13];
    const float* b3  = (const float*)d_in[14];
    float* out = (float*)d_out;

    const int N = in_sizes[0] / 128;
    const int E = in_sizes[1];

    float *fA, *fB, *el, *er, *s;
    cudaGetSymbolAddress((void**)&fA, g_fA);
    cudaGetSymbolAddress((void**)&fB, g_fB);
    cudaGetSymbolAddress((void**)&el, g_el);
    cudaGetSymbolAddress((void**)&er, g_er);
    cudaGetSymbolAddress((void**)&s,  g_s);

    const int SMEM128 = (64 * 129 + 128 * 128) * (int)sizeof(float);
    const int SMEM32  = (64 * 129 + 128 * 32)  * (int)sizeof(float);
    cudaFuncSetAttribute(gemm_kernel<128>, cudaFuncAttributeMaxDynamicSharedMemorySize, SMEM128);
    cudaFuncSetAttribute(gemm_kernel<32>,  cudaFuncAttributeMaxDynamicSharedMemorySize, SMEM32);

    const int gemm_blocks = (N + 63) / 64;
    const int edge_blocks = (E * 32 + 255) / 256;
    const int nHD  = N * 128;
    const int nHD3 = N * 32;

    // ---------------- Layer 1 ----------------
    zero_kernel<<<(nHD / 4 + 255) / 256, 256>>>(fB, nHD / 4);
    zero_kernel<<<(N + 255) / 256, 256>>>(s, N);           // N*4/4 float4s
    gemm_kernel<128><<<gemm_blocks, 256, SMEM128>>>(x, W1, fA, N);
    attn_kernel<4, 32><<<(N * 4 + 255) / 256, 256>>>(fA, al1, ar1, el, er, N);
    edge_kernel<4, 32><<<edge_blocks, 256>>>(fA, el, er, src, dst, fB, s, E);
    norm_kernel<4, 32, true><<<(nHD + 255) / 256, 256>>>(fB, s, b1, fB, N);

    // ---------------- Layer 2 ----------------
    gemm_kernel<128><<<gemm_blocks, 256, SMEM128>>>(fB, W2, fA, N);
    zero_kernel<<<(nHD / 4 + 255) / 256, 256>>>(fB, nHD / 4);
    zero_kernel<<<(N + 255) / 256, 256>>>(s, N);
    attn_kernel<4, 32><<<(N * 4 + 255) / 256, 256>>>(fA, al2, ar2, el, er, N);
    edge_kernel<4, 32><<<edge_blocks, 256>>>(fA, el, er, src, dst, fB, s, E);
    norm_kernel<4, 32, true><<<(nHD + 255) / 256, 256>>>(fB, s, b2, fB, N);

    // ---------------- Layer 3 ----------------
    gemm_kernel<32><<<gemm_blocks, 64, SMEM32>>>(fB, W3, fA, N);
    zero_kernel<<<(nHD3 / 4 + 255) / 256, 256>>>(out, nHD3 / 4);
    zero_kernel<<<(N + 255) / 256, 256>>>(s, N);
    attn_kernel<1, 32><<<(N + 255) / 256, 256>>>(fA, al3, ar3, el, er, N);
    edge_kernel<1, 32><<<edge_blocks, 256>>>(fA, el, er, src, dst, out, s, E);
    norm_kernel<1, 32, false><<<(nHD3 + 255) / 256, 256>>>(out, s, b3, out, N);
}

// round 2
// speedup vs baseline: 1.0737x; 1.0737x over previous
#include <cuda_runtime.h>
#include <cuda_bf16.h>
#include <cstdint>

#define NN 100000
#define NE 1600000

// Static scratch (no allocations allowed)
__device__ float g_fA[(size_t)NN * 128];   // projected features f
__device__ float g_fB[(size_t)NN * 128];   // accumulator / next-layer input h
__device__ float g_el[NN * 4];
__device__ float g_er[NN * 4];
__device__ float g_s[NN * 4];

// ---------------------------------------------------------------------------
// packed f32x2 helpers
__device__ __forceinline__ uint64_t dup_f32(float a) {
    uint64_t r;
    asm("mov.b64 %0, {%1, %1};" : "=l"(r) : "f"(a));
    return r;
}
__device__ __forceinline__ void fma2(uint64_t& c, uint64_t a, uint64_t b) {
    asm("fma.rn.f32x2 %0, %1, %2, %0;" : "+l"(c) : "l"(a), "l"(b));
}
__device__ __forceinline__ float2 unpk(uint64_t v) {
    float2 r;
    asm("mov.b64 {%0, %1}, %2;" : "=f"(r.x), "=f"(r.y) : "l"(v));
    return r;
}

// ---------------------------------------------------------------------------
// Fused GEMM: F[N,COLS] = norm(X)[N,128] @ W[128,COLS], plus attention scores
// el/er = sum_d F*al / F*ar computed in the epilogue.
// NORM: X element is raw accumulator; apply accum/max(s,1e-9)+b then ELU
//       (input layout is always H_in=4, D_in=32 when NORM is true).
// BR=64 rows/block, thread tile 4 rows x 8 cols, blockDim = 16*(COLS/8).
template <int COLS, bool NORM, int H>
__global__ void gemm_attn_kernel(const float* __restrict__ X, const float* __restrict__ W,
                                 const float* __restrict__ s_in, const float* __restrict__ b_in,
                                 const float* __restrict__ al, const float* __restrict__ ar,
                                 float* __restrict__ F, float* __restrict__ el,
                                 float* __restrict__ er, int nrows) {
    constexpr int K  = 128;
    constexpr int BR = 64;
    extern __shared__ float sm[];
    float (*Xs)[K + 1] = (float(*)[K + 1])sm;       // [BR][129]
    float* Ws = sm + BR * (K + 1);                  // [K][COLS]

    const int tid  = threadIdx.x;
    const int nth  = blockDim.x;
    const int row0 = blockIdx.x * BR;

    // load W into smem
    for (int i = tid; i < K * COLS / 4; i += nth)
        ((float4*)Ws)[i] = ((const float4*)W)[i];

    // load X tile (optionally normalized: v = elu(accum/s + b))
    for (int i = tid; i < BR * (K / 4); i += nth) {
        int r  = i / (K / 4);
        int k4 = i % (K / 4);
        int row = row0 + r;
        float4 v = make_float4(0.f, 0.f, 0.f, 0.f);
        if (row < nrows) {
            v = ((const float4*)(X + (size_t)row * K))[k4];
            if (NORM) {
                int c = k4 * 4;
                int h = c / 32;
                float inv = 1.f / fmaxf(s_in[row * 4 + h], 1e-9f);
                v.x = v.x * inv + b_in[c + 0];
                v.y = v.y * inv + b_in[c + 1];
                v.z = v.z * inv + b_in[c + 2];
                v.w = v.w * inv + b_in[c + 3];
                v.x = v.x > 0.f ? v.x : expm1f(v.x);
                v.y = v.y > 0.f ? v.y : expm1f(v.y);
                v.z = v.z > 0.f ? v.z : expm1f(v.z);
                v.w = v.w > 0.f ? v.w : expm1f(v.w);
            }
        }
        Xs[r][k4 * 4 + 0] = v.x; Xs[r][k4 * 4 + 1] = v.y;
        Xs[r][k4 * 4 + 2] = v.z; Xs[r][k4 * 4 + 3] = v.w;
    }
    __syncthreads();

    const int rc = tid % 16;    // row group (4 rows)
    const int cc = tid / 16;    // col group (8 cols)

    uint64_t acc2[4][4] = {};   // 4 rows x 4 f32x2 col-pairs

#pragma unroll 2
    for (int k = 0; k < K; k++) {
        const ulonglong2* bp = (const ulonglong2*)&Ws[k * COLS + cc * 8];
        ulonglong2 b01 = bp[0];
        ulonglong2 b23 = bp[1];
#pragma unroll
        for (int i = 0; i < 4; i++) {
            uint64_t a2 = dup_f32(Xs[rc * 4 + i][k]);
            fma2(acc2[i][0], a2, b01.x);
            fma2(acc2[i][1], a2, b01.y);
            fma2(acc2[i][2], a2, b23.x);
            fma2(acc2[i][3], a2, b23.y);
        }
    }

    // attention vectors for my 8 columns (flat index == column since COLS==H*D)
    float al8[8], ar8[8];
#pragma unroll
    for (int j = 0; j < 8; j++) {
        al8[j] = __ldg(al + cc * 8 + j);
        ar8[j] = __ldg(ar + cc * 8 + j);
    }

    float slp[4], srp[4];
#pragma unroll
    for (int i = 0; i < 4; i++) {
        float o[8];
#pragma unroll
        for (int j2 = 0; j2 < 4; j2++) {
            float2 p = unpk(acc2[i][j2]);
            o[2 * j2] = p.x; o[2 * j2 + 1] = p.y;
        }
        int row = row0 + rc * 4 + i;
        if (row < nrows) {
            *(float4*)(F + (size_t)row * COLS + cc * 8)     = make_float4(o[0], o[1], o[2], o[3]);
            *(float4*)(F + (size_t)row * COLS + cc * 8 + 4) = make_float4(o[4], o[5], o[6], o[7]);
        }
        float sl = 0.f, sr = 0.f;
#pragma unroll
        for (int j = 0; j < 8; j++) { sl = fmaf(o[j], al8[j], sl); sr = fmaf(o[j], ar8[j], sr); }
        slp[i] = sl; srp[i] = sr;
    }

    // smem reduction of el/er partials (reuse Xs region)
    __syncthreads();
    float* red = sm;            // [BR][H][2]
    for (int i = tid; i < BR * H * 2; i += nth) red[i] = 0.f;
    __syncthreads();
    int h = (cc * 8) / 32;      // head of my 8 columns (0 when COLS==32)
    if (H == 1) h = 0;
#pragma unroll
    for (int i = 0; i < 4; i++) {
        int r = rc * 4 + i;
        atomicAdd(&red[(r * H + h) * 2 + 0], slp[i]);
        atomicAdd(&red[(r * H + h) * 2 + 1], srp[i]);
    }
    __syncthreads();
    for (int i = tid; i < BR * H; i += nth) {
        int r = i / H, hh = i % H;
        int row = row0 + r;
        if (row < nrows) {
            el[row * H + hh] = red[i * 2 + 0];
            er[row * H + hh] = red[i * 2 + 1];
        }
    }
}

// ---------------------------------------------------------------------------
// One warp per edge (H=4, D=32): w = exp(leakyrelu(el[src]+er[dst])) per head.
// (segment-max shift dropped: alpha = w/s invariant, scores are O(1))
__global__ void edge4_kernel(const float* __restrict__ F, const float* __restrict__ el,
                             const float* __restrict__ er, const int* __restrict__ src,
                             const int* __restrict__ dst, float* __restrict__ accum,
                             float* __restrict__ s, int E) {
    int warp_id = (blockIdx.x * blockDim.x + threadIdx.x) >> 5;
    int lane    = threadIdx.x & 31;
    if (warp_id >= E) return;

    int sn = __ldg(src + warp_id);
    int dn = __ldg(dst + warp_id);

    float w = 0.f;
    if (lane < 4) {
        float v = __ldg(el + sn * 4 + lane) + __ldg(er + dn * 4 + lane);
        v = v > 0.f ? v : 0.2f * v;
        w = __expf(v);
    }
    float w0 = __shfl_sync(0xffffffffu, w, 0);
    float w1 = __shfl_sync(0xffffffffu, w, 1);
    float w2 = __shfl_sync(0xffffffffu, w, 2);
    float w3 = __shfl_sync(0xffffffffu, w, 3);
    if (lane == 0)
        asm volatile("red.global.add.v4.f32 [%0], {%1,%2,%3,%4};"
                     :: "l"(s + dn * 4), "f"(w0), "f"(w1), "f"(w2), "f"(w3) : "memory");

    float wh = (lane < 8) ? w0 : (lane < 16) ? w1 : (lane < 24) ? w2 : w3;
    float4 fv = *(const float4*)(F + (size_t)sn * 128 + lane * 4);
    float* ap = accum + (size_t)dn * 128 + lane * 4;
    asm volatile("red.global.add.v4.f32 [%0], {%1,%2,%3,%4};"
                 :: "l"(ap), "f"(fv.x * wh), "f"(fv.y * wh),
                    "f"(fv.z * wh), "f"(fv.w * wh) : "memory");
}

// ---------------------------------------------------------------------------
// Layer-3 edge kernel (H=1, D=32): 4 edges per warp, 8 lanes each.
__global__ void edge3_kernel(const float* __restrict__ F, const float* __restrict__ el,
                             const float* __restrict__ er, const int* __restrict__ src,
                             const int* __restrict__ dst, float* __restrict__ accum,
                             float* __restrict__ s, int E) {
    int gt   = blockIdx.x * blockDim.x + threadIdx.x;
    int warp = gt >> 5;
    int lane = gt & 31;
    int e    = warp * 4 + (lane >> 3);
    int sub  = lane & 7;
    bool ok  = e < E;

    int sn = 0, dn = 0;
    if (ok) { sn = __ldg(src + e); dn = __ldg(dst + e); }

    float w = 0.f;
    if (ok && sub == 0) {
        float v = __ldg(el + sn) + __ldg(er + dn);
        v = v > 0.f ? v : 0.2f * v;
        w = __expf(v);
        asm volatile("red.global.add.f32 [%0], %1;" :: "l"(s + dn), "f"(w) : "memory");
    }
    w = __shfl_sync(0xffffffffu, w, lane & 24);
    if (ok) {
        float4 fv = *(const float4*)(F + (size_t)sn * 32 + sub * 4);
        float* ap = accum + (size_t)dn * 32 + sub * 4;
        asm volatile("red.global.add.v4.f32 [%0], {%1,%2,%3,%4};"
                     :: "l"(ap), "f"(fv.x * w), "f"(fv.y * w),
                        "f"(fv.z * w), "f"(fv.w * w) : "memory");
    }
}

// ---------------------------------------------------------------------------
// Final normalize: out = accum/max(s,1e-9) + b (no ELU), H=1, D=32.
__global__ void norm3_kernel(const float* __restrict__ accum, const float* __restrict__ s,
                             const float* __restrict__ b, float* __restrict__ out, int n) {
    int i = blockIdx.x * blockDim.x + threadIdx.x;
    if (i >= n * 32) return;
    int c = i % 32;
    int node = i / 32;
    float sv = s[node];
    out[i] = accum[i] / fmaxf(sv, 1e-9f) + b[c];
}

// ---------------------------------------------------------------------------
extern "C" void kernel_launch(void* const* d_in, const int* in_sizes, int n_in,
                              void* d_out, int out_size) {
    const float* x   = (const float*)d_in[0];
    const int*   src = (const int*)d_in[1];
    const int*   dst = (const int*)d_in[2];
    const float* W1  = (const float*)d_in[3];
    const float* al1 = (const float*)d_in[4];
    const float* ar1 = (const float*)d_in[5];
    const float* b1  = (const float*)d_in[6];
    const float* W2  = (const float*)d_in[7];
    const float* al2 = (const float*)d_in[8];
    const float* ar2 = (const float*)d_in[9];
    const float* b2  = (const float*)d_in[10];
    const float* W3  = (const float*)d_in[11];
    const float* al3 = (const float*)d_in[12];
    const float* ar3 = (const float*)d_in[13];
    const float* b3  = (const float*)d_in[14];
    float* out = (float*)d_out;

    const int N = in_sizes[0] / 128;
    const int E = in_sizes[1];

    float *fA, *fB, *el, *er, *s;
    cudaGetSymbolAddress((void**)&fA, g_fA);
    cudaGetSymbolAddress((void**)&fB, g_fB);
    cudaGetSymbolAddress((void**)&el, g_el);
    cudaGetSymbolAddress((void**)&er, g_er);
    cudaGetSymbolAddress((void**)&s,  g_s);

    const int SMEM128 = (64 * 129 + 128 * 128) * (int)sizeof(float);
    const int SMEM32  = (64 * 129 + 128 * 32)  * (int)sizeof(float);
    cudaFuncSetAttribute((const void*)gemm_attn_kernel<128, false, 4>,
                         cudaFuncAttributeMaxDynamicSharedMemorySize, SMEM128);
    cudaFuncSetAttribute((const void*)gemm_attn_kernel<128, true, 4>,
                         cudaFuncAttributeMaxDynamicSharedMemorySize, SMEM128);
    cudaFuncSetAttribute((const void*)gemm_attn_kernel<32, true, 1>,
                         cudaFuncAttributeMaxDynamicSharedMemorySize, SMEM32);

    const int gemm_blocks = (N + 63) / 64;
    const int edge4_blocks = (E * 32 + 255) / 256;
    const int edge3_blocks = (((E + 3) / 4) * 32 + 255) / 256;

    // ---------------- Layer 1 ----------------
    cudaMemsetAsync(fB, 0, (size_t)N * 128 * sizeof(float));
    cudaMemsetAsync(s,  0, (size_t)N * 4 * sizeof(float));
    gemm_attn_kernel<128, false, 4><<<gemm_blocks, 256, SMEM128>>>(
        x, W1, nullptr, nullptr, al1, ar1, fA, el, er, N);
    edge4_kernel<<<edge4_blocks, 256>>>(fA, el, er, src, dst, fB, s, E);

    // ---------------- Layer 2 ----------------
    gemm_attn_kernel<128, true, 4><<<gemm_blocks, 256, SMEM128>>>(
        fB, W2, s, b1, al2, ar2, fA, el, er, N);
    cudaMemsetAsync(fB, 0, (size_t)N * 128 * sizeof(float));
    cudaMemsetAsync(s,  0, (size_t)N * 4 * sizeof(float));
    edge4_kernel<<<edge4_blocks, 256>>>(fA, el, er, src, dst, fB, s, E);

    // ---------------- Layer 3 ----------------
    gemm_attn_kernel<32, true, 1><<<gemm_blocks, 64, SMEM32>>>(
        fB, W3, s, b2, al3, ar3, fA, el, er, N);
    cudaMemsetAsync(out, 0, (size_t)N * 32 * sizeof(float));
    cudaMemsetAsync(s,   0, (size_t)N * 4 * sizeof(float));
    edge3_kernel<<<edge3_blocks, 256>>>(fA, el, er, src, dst, out, s, E);
    norm3_kernel<<<(N * 32 + 255) / 256, 256>>>(out, s, b3, out, N);
}

// round 3
// speedup vs baseline: 1.7514x; 1.6312x over previous
#include <cuda_runtime.h>
#include <cuda_bf16.h>
#include <cstdint>

#define NN 100000
#define NE 1600000
#define NB_SCAN ((NN + 1023) / 1024)

// Static scratch (no allocations allowed)
__device__ float g_fA[(size_t)NN * 128];
__device__ float g_fB[(size_t)NN * 128];
__device__ float g_el[NN * 4];
__device__ float g_er[NN * 4];
__device__ int   g_deg[NN];        // histogram, then reused as scatter cursor
__device__ int   g_off[NN + 1];    // CSR offsets
__device__ int   g_esrc[NE];       // src node of each edge, grouped by dst
__device__ int   g_bsum[NB_SCAN];
__device__ int   g_boff[NB_SCAN];

// ---------------------------------------------------------------------------
// packed f32x2 helpers
__device__ __forceinline__ uint64_t dup_f32(float a) {
    uint64_t r;
    asm("mov.b64 %0, {%1, %1};" : "=l"(r) : "f"(a));
    return r;
}
__device__ __forceinline__ void fma2(uint64_t& c, uint64_t a, uint64_t b) {
    asm("fma.rn.f32x2 %0, %1, %2, %0;" : "+l"(c) : "l"(a), "l"(b));
}
__device__ __forceinline__ float2 unpk(uint64_t v) {
    float2 r;
    asm("mov.b64 {%0, %1}, %2;" : "=f"(r.x), "=f"(r.y) : "l"(v));
    return r;
}

// ===========================================================================
// CSR build: histogram -> scan -> scatter
// ===========================================================================
__global__ void hist_kernel(const int* __restrict__ dst, int* __restrict__ deg, int E) {
    int i = blockIdx.x * blockDim.x + threadIdx.x;
    if (i < E) atomicAdd(&deg[dst[i]], 1);
}

// block b sums deg[b*1024 .. b*1024+1023]
__global__ void bsum_kernel(const int* __restrict__ deg, int* __restrict__ bsum, int n) {
    __shared__ int sm[256];
    int base = blockIdx.x * 1024;
    int t = threadIdx.x;
    int s = 0;
    for (int j = 0; j < 4; j++) {
        int idx = base + t + j * 256;
        if (idx < n) s += deg[idx];
    }
    sm[t] = s;
    __syncthreads();
    for (int d = 128; d > 0; d >>= 1) {
        if (t < d) sm[t] += sm[t + d];
        __syncthreads();
    }
    if (t == 0) bsum[blockIdx.x] = sm[0];
}

// exclusive scan of block sums (NB_SCAN <= 128), also writes total to off[NN]
__global__ void bscan_kernel(const int* __restrict__ bsum, int* __restrict__ boff,
                             int* __restrict__ off, int nb, int n) {
    __shared__ int sm[128];
    int t = threadIdx.x;
    sm[t] = (t < nb) ? bsum[t] : 0;
    __syncthreads();
    for (int d = 1; d < 128; d <<= 1) {
        int x = (t >= d) ? sm[t - d] : 0;
        __syncthreads();
        sm[t] += x;
        __syncthreads();
    }
    if (t < nb) boff[t] = (t > 0) ? sm[t - 1] : 0;
    if (t == 127) off[n] = sm[127];
}

// per-chunk exclusive scan, offset by boff
__global__ void scan_chunk_kernel(const int* __restrict__ deg, const int* __restrict__ boff,
                                  int* __restrict__ off, int n) {
    __shared__ int sm[256];
    int base = blockIdx.x * 1024;
    int t = threadIdx.x;
    int v[4];
    int s = 0;
    for (int j = 0; j < 4; j++) {
        int idx = base + t * 4 + j;
        v[j] = (idx < n) ? deg[idx] : 0;
        s += v[j];
    }
    sm[t] = s;
    __syncthreads();
    for (int d = 1; d < 256; d <<= 1) {
        int x = (t >= d) ? sm[t - d] : 0;
        __syncthreads();
        sm[t] += x;
        __syncthreads();
    }
    int run = ((t > 0) ? sm[t - 1] : 0) + boff[blockIdx.x];
    for (int j = 0; j < 4; j++) {
        int idx = base + t * 4 + j;
        if (idx < n) off[idx] = run;
        run += v[j];
    }
}

__global__ void scatter_kernel(const int* __restrict__ src, const int* __restrict__ dst,
                               const int* __restrict__ off, int* __restrict__ cursor,
                               int* __restrict__ esrc, int E) {
    int i = blockIdx.x * blockDim.x + threadIdx.x;
    if (i >= E) return;
    int dn = dst[i];
    int pos = off[dn] + atomicAdd(&cursor[dn], 1);
    esrc[pos] = src[i];
}

// ===========================================================================
// Fused GEMM + attention scores: F = X @ W; el/er = sum_d F*al / F*ar.
// BR=64 rows/block, thread tile 4 rows x 8 cols, blockDim = 16*(COLS/8).
// ===========================================================================
template <int COLS, int H>
__global__ void gemm_attn_kernel(const float* __restrict__ X, const float* __restrict__ W,
                                 const float* __restrict__ al, const float* __restrict__ ar,
                                 float* __restrict__ F, float* __restrict__ el,
                                 float* __restrict__ er, int nrows) {
    constexpr int K  = 128;
    constexpr int BR = 64;
    extern __shared__ float sm[];
    float (*Xs)[K + 1] = (float(*)[K + 1])sm;       // [BR][129]
    float* Ws = sm + BR * (K + 1);                  // [K][COLS]

    const int tid  = threadIdx.x;
    const int nth  = blockDim.x;
    const int row0 = blockIdx.x * BR;

    for (int i = tid; i < K * COLS / 4; i += nth)
        ((float4*)Ws)[i] = ((const float4*)W)[i];

    for (int i = tid; i < BR * (K / 4); i += nth) {
        int r  = i / (K / 4);
        int k4 = i % (K / 4);
        int row = row0 + r;
        float4 v = make_float4(0.f, 0.f, 0.f, 0.f);
        if (row < nrows) v = ((const float4*)(X + (size_t)row * K))[k4];
        Xs[r][k4 * 4 + 0] = v.x; Xs[r][k4 * 4 + 1] = v.y;
        Xs[r][k4 * 4 + 2] = v.z; Xs[r][k4 * 4 + 3] = v.w;
    }
    __syncthreads();

    const int rc = tid % 16;
    const int cc = tid / 16;

    uint64_t acc2[4][4] = {};

#pragma unroll 2
    for (int k = 0; k < K; k++) {
        const ulonglong2* bp = (const ulonglong2*)&Ws[k * COLS + cc * 8];
        ulonglong2 b01 = bp[0];
        ulonglong2 b23 = bp[1];
#pragma unroll
        for (int i = 0; i < 4; i++) {
            uint64_t a2 = dup_f32(Xs[rc * 4 + i][k]);
            fma2(acc2[i][0], a2, b01.x);
            fma2(acc2[i][1], a2, b01.y);
            fma2(acc2[i][2], a2, b23.x);
            fma2(acc2[i][3], a2, b23.y);
        }
    }

    float al8[8], ar8[8];
#pragma unroll
    for (int j = 0; j < 8; j++) {
        al8[j] = __ldg(al + cc * 8 + j);
        ar8[j] = __ldg(ar + cc * 8 + j);
    }

    float slp[4], srp[4];
#pragma unroll
    for (int i = 0; i < 4; i++) {
        float o[8];
#pragma unroll
        for (int j2 = 0; j2 < 4; j2++) {
            float2 p = unpk(acc2[i][j2]);
            o[2 * j2] = p.x; o[2 * j2 + 1] = p.y;
        }
        int row = row0 + rc * 4 + i;
        if (row < nrows) {
            *(float4*)(F + (size_t)row * COLS + cc * 8)     = make_float4(o[0], o[1], o[2], o[3]);
            *(float4*)(F + (size_t)row * COLS + cc * 8 + 4) = make_float4(o[4], o[5], o[6], o[7]);
        }
        float sl = 0.f, sr = 0.f;
#pragma unroll
        for (int j = 0; j < 8; j++) { sl = fmaf(o[j], al8[j], sl); sr = fmaf(o[j], ar8[j], sr); }
        slp[i] = sl; srp[i] = sr;
    }

    __syncthreads();
    float* red = sm;            // [BR][H][2]
    for (int i = tid; i < BR * H * 2; i += nth) red[i] = 0.f;
    __syncthreads();
    int h = (H == 1) ? 0 : (cc * 8) / 32;
#pragma unroll
    for (int i = 0; i < 4; i++) {
        int r = rc * 4 + i;
        atomicAdd(&red[(r * H + h) * 2 + 0], slp[i]);
        atomicAdd(&red[(r * H + h) * 2 + 1], srp[i]);
    }
    __syncthreads();
    for (int i = tid; i < BR * H; i += nth) {
        int r = i / H, hh = i % H;
        int row = row0 + r;
        if (row < nrows) {
            el[row * H + hh] = red[i * 2 + 0];
            er[row * H + hh] = red[i * 2 + 1];
        }
    }
}

// ===========================================================================
// CSR edge aggregation + fused normalize/bias/ELU.
// One warp per dst node. w = exp(leakyrelu(el[src]+er[dst])) per head.
// (segment-max shift dropped: alpha = w/s invariant, scores are O(1))
// H=4: lane owns 4 floats (head = lane/8). H=1: lane owns 1 float.
// ===========================================================================
template <int H, bool ELU>
__global__ void edge_csr_kernel(const float* __restrict__ F, const float* __restrict__ el,
                                const float* __restrict__ er, const int* __restrict__ off,
                                const int* __restrict__ esrc, const float* __restrict__ b,
                                float* __restrict__ out, int n) {
    constexpr int HD = H * 32;
    int warp = (blockIdx.x * blockDim.x + threadIdx.x) >> 5;
    int lane = threadIdx.x & 31;
    if (warp >= n) return;
    const int node = warp;

    float erh;
    if (H == 4) {
        float4 e4 = *(const float4*)(er + node * 4);
        erh = lane < 8 ? e4.x : lane < 16 ? e4.y : lane < 24 ? e4.z : e4.w;
    } else {
        erh = __ldg(er + node);
    }

    const int start = off[node], end = off[node + 1];
    float acc0 = 0.f, acc1 = 0.f, acc2 = 0.f, acc3 = 0.f, s = 0.f;

    for (int base = start; base < end; base += 32) {
        int cnt = min(32, end - base);
        int sidx = (base + lane < end) ? __ldg(esrc + base + lane) : 0;
        for (int j = 0; j < cnt; j++) {
            int sn = __shfl_sync(0xffffffffu, sidx, j);
            float elh;
            if (H == 4) {
                float4 e4 = *(const float4*)(el + sn * 4);
                elh = lane < 8 ? e4.x : lane < 16 ? e4.y : lane < 24 ? e4.z : e4.w;
            } else {
                elh = __ldg(el + sn);
            }
            float v = elh + erh;
            v = v > 0.f ? v : 0.2f * v;
            float w = __expf(v);
            s += w;
            if (H == 4) {
                float4 f4 = *(const float4*)(F + (size_t)sn * 128 + lane * 4);
                acc0 = fmaf(w, f4.x, acc0);
                acc1 = fmaf(w, f4.y, acc1);
                acc2 = fmaf(w, f4.z, acc2);
                acc3 = fmaf(w, f4.w, acc3);
            } else {
                float f = __ldg(F + (size_t)sn * 32 + lane);
                acc0 = fmaf(w, f, acc0);
            }
        }
    }

    float inv = 1.f / fmaxf(s, 1e-9f);
    if (H == 4) {
        int c = lane * 4;
        float4 o;
        o.x = acc0 * inv + b[c + 0];
        o.y = acc1 * inv + b[c + 1];
        o.z = acc2 * inv + b[c + 2];
        o.w = acc3 * inv + b[c + 3];
        if (ELU) {
            o.x = o.x > 0.f ? o.x : expm1f(o.x);
            o.y = o.y > 0.f ? o.y : expm1f(o.y);
            o.z = o.z > 0.f ? o.z : expm1f(o.z);
            o.w = o.w > 0.f ? o.w : expm1f(o.w);
        }
        *(float4*)(out + (size_t)node * HD + c) = o;
    } else {
        float o = acc0 * inv + b[lane];
        if (ELU) o = o > 0.f ? o : expm1f(o);
        out[(size_t)node * HD + lane] = o;
    }
}

// ===========================================================================
extern "C" void kernel_launch(void* const* d_in, const int* in_sizes, int n_in,
                              void* d_out, int out_size) {
    const float* x   = (const float*)d_in[0];
    const int*   src = (const int*)d_in[1];
    const int*   dst = (const int*)d_in[2];
    const float* W1  = (const float*)d_in[3];
    const float* al1 = (const float*)d_in[4];
    const float* ar1 = (const float*)d_in[5];
    const float* b1  = (const float*)d_in[6];
    const float* W2  = (const float*)d_in[7];
    const float* al2 = (const float*)d_in[8];
    const float* ar2 = (const float*)d_in[9];
    const float* b2  = (const float*)d_in[10];
    const float* W3  = (const float*)d_in[11];
    const float* al3 = (const float*)d_in[12];
    const float* ar3 = (const float*)d_in[13];
    const float* b3  = (const float*)d_in[14];
    float* out = (float*)d_out;

    const int N = in_sizes[0] / 128;
    const int E = in_sizes[1];

    float *fA, *fB, *el, *er;
    int *deg, *off, *esrc, *bsum, *boff;
    cudaGetSymbolAddress((void**)&fA, g_fA);
    cudaGetSymbolAddress((void**)&fB, g_fB);
    cudaGetSymbolAddress((void**)&el, g_el);
    cudaGetSymbolAddress((void**)&er, g_er);
    cudaGetSymbolAddress((void**)&deg, g_deg);
    cudaGetSymbolAddress((void**)&off, g_off);
    cudaGetSymbolAddress((void**)&esrc, g_esrc);
    cudaGetSymbolAddress((void**)&bsum, g_bsum);
    cudaGetSymbolAddress((void**)&boff, g_boff);

    const int SMEM128 = (64 * 129 + 128 * 128) * (int)sizeof(float);
    const int SMEM32  = (64 * 129 + 128 * 32)  * (int)sizeof(float);
    cudaFuncSetAttribute((const void*)gemm_attn_kernel<128, 4>,
                         cudaFuncAttributeMaxDynamicSharedMemorySize, SMEM128);
    cudaFuncSetAttribute((const void*)gemm_attn_kernel<32, 1>,
                         cudaFuncAttributeMaxDynamicSharedMemorySize, SMEM32);

    const int gemm_blocks = (N + 63) / 64;
    const int eblk = (E + 255) / 256;
    const int nb   = (N + 1023) / 1024;
    const int edge_blocks = (N * 32 + 255) / 256;

    // ---------------- CSR build (reused by all 3 layers) ----------------
    cudaMemsetAsync(deg, 0, (size_t)N * sizeof(int));
    hist_kernel<<<eblk, 256>>>(dst, deg, E);
    bsum_kernel<<<nb, 256>>>(deg, bsum, N);
    bscan_kernel<<<1, 128>>>(bsum, boff, off, nb, N);
    scan_chunk_kernel<<<nb, 256>>>(deg, boff, off, N);
    cudaMemsetAsync(deg, 0, (size_t)N * sizeof(int));
    scatter_kernel<<<eblk, 256>>>(src, dst, off, deg, esrc, E);

    // ---------------- Layer 1 ----------------
    gemm_attn_kernel<128, 4><<<gemm_blocks, 256, SMEM128>>>(
        x, W1, al1, ar1, fA, el, er, N);
    edge_csr_kernel<4, true><<<edge_blocks, 256>>>(fA, el, er, off, esrc, b1, fB, N);

    // ---------------- Layer 2 ----------------
    gemm_attn_kernel<128, 4><<<gemm_blocks, 256, SMEM128>>>(
        fB, W2, al2, ar2, fA, el, er, N);
    edge_csr_kernel<4, true><<<edge_blocks, 256>>>(fA, el, er, off, esrc, b2, fB, N);

    // ---------------- Layer 3 ----------------
    gemm_attn_kernel<32, 1><<<gemm_blocks, 64, SMEM32>>>(
        fB, W3, al3, ar3, fA, el, er, N);
    edge_csr_kernel<1, false><<<edge_blocks, 256>>>(fA, el, er, off, esrc, b3, out, N);
}

// round 4
// speedup vs baseline: 1.7956x; 1.0252x over previous
#include <cuda_runtime.h>
#include <cuda_fp16.h>
#include <cstdint>

#define NN 100000
#define NE 1600000
#define NB_SCAN ((NN + 1023) / 1024)

// Static scratch (no allocations allowed)
__device__ __half g_fH[(size_t)NN * 128];  // projected features (fp16 gather payload)
__device__ float  g_fB[(size_t)NN * 128];  // inter-layer node features (fp32)
__device__ float  g_el[NN * 4];
__device__ float  g_er[NN * 4];
__device__ int    g_deg[NN];
__device__ int    g_off[NN + 1];
__device__ int    g_esrc[NE];
__device__ int    g_bsum[NB_SCAN];
__device__ int    g_boff[NB_SCAN];

// ---------------------------------------------------------------------------
// packed f32x2 helpers
__device__ __forceinline__ uint64_t dup_f32(float a) {
    uint64_t r;
    asm("mov.b64 %0, {%1, %1};" : "=l"(r) : "f"(a));
    return r;
}
__device__ __forceinline__ void fma2(uint64_t& c, uint64_t a, uint64_t b) {
    asm("fma.rn.f32x2 %0, %1, %2, %0;" : "+l"(c) : "l"(a), "l"(b));
}
__device__ __forceinline__ float2 unpk(uint64_t v) {
    float2 r;
    asm("mov.b64 {%0, %1}, %2;" : "=f"(r.x), "=f"(r.y) : "l"(v));
    return r;
}

// ===========================================================================
// CSR build: histogram -> scan -> scatter
// ===========================================================================
__global__ void hist_kernel(const int* __restrict__ dst, int* __restrict__ deg, int E) {
    int i = blockIdx.x * blockDim.x + threadIdx.x;
    if (i < E) atomicAdd(&deg[dst[i]], 1);
}

__global__ void bsum_kernel(const int* __restrict__ deg, int* __restrict__ bsum, int n) {
    __shared__ int sm[256];
    int base = blockIdx.x * 1024;
    int t = threadIdx.x;
    int s = 0;
    for (int j = 0; j < 4; j++) {
        int idx = base + t + j * 256;
        if (idx < n) s += deg[idx];
    }
    sm[t] = s;
    __syncthreads();
    for (int d = 128; d > 0; d >>= 1) {
        if (t < d) sm[t] += sm[t + d];
        __syncthreads();
    }
    if (t == 0) bsum[blockIdx.x] = sm[0];
}

__global__ void bscan_kernel(const int* __restrict__ bsum, int* __restrict__ boff,
                             int* __restrict__ off, int nb, int n) {
    __shared__ int sm[128];
    int t = threadIdx.x;
    sm[t] = (t < nb) ? bsum[t] : 0;
    __syncthreads();
    for (int d = 1; d < 128; d <<= 1) {
        int x = (t >= d) ? sm[t - d] : 0;
        __syncthreads();
        sm[t] += x;
        __syncthreads();
    }
    if (t < nb) boff[t] = (t > 0) ? sm[t - 1] : 0;
    if (t == 127) off[n] = sm[127];
}

__global__ void scan_chunk_kernel(const int* __restrict__ deg, const int* __restrict__ boff,
                                  int* __restrict__ off, int n) {
    __shared__ int sm[256];
    int base = blockIdx.x * 1024;
    int t = threadIdx.x;
    int v[4];
    int s = 0;
    for (int j = 0; j < 4; j++) {
        int idx = base + t * 4 + j;
        v[j] = (idx < n) ? deg[idx] : 0;
        s += v[j];
    }
    sm[t] = s;
    __syncthreads();
    for (int d = 1; d < 256; d <<= 1) {
        int x = (t >= d) ? sm[t - d] : 0;
        __syncthreads();
        sm[t] += x;
        __syncthreads();
    }
    int run = ((t > 0) ? sm[t - 1] : 0) + boff[blockIdx.x];
    for (int j = 0; j < 4; j++) {
        int idx = base + t * 4 + j;
        if (idx < n) off[idx] = run;
        run += v[j];
    }
}

__global__ void scatter_kernel(const int* __restrict__ src, const int* __restrict__ dst,
                               const int* __restrict__ off, int* __restrict__ cursor,
                               int* __restrict__ esrc, int E) {
    int i = blockIdx.x * blockDim.x + threadIdx.x;
    if (i >= E) return;
    int dn = dst[i];
    int pos = off[dn] + atomicAdd(&cursor[dn], 1);
    esrc[pos] = src[i];
}

// ===========================================================================
// Fused GEMM + attention scores: F(half) = X @ W; el/er from fp32 result.
// A-tile stored transposed in smem: Xs[k][r] -> one LDS.128 per k.
// BR=64 rows/block, thread tile 4 rows x 8 cols, blockDim = 16*(COLS/8).
// ===========================================================================
template <int COLS, int H>
__global__ void gemm_attn_kernel(const float* __restrict__ X, const float* __restrict__ W,
                                 const float* __restrict__ al, const float* __restrict__ ar,
                                 __half* __restrict__ F, float* __restrict__ el,
                                 float* __restrict__ er, int nrows) {
    constexpr int K    = 128;
    constexpr int BR   = 64;
    constexpr int XPAD = BR + 4;     // float4-aligned row stride
    extern __shared__ float sm[];
    float* Xs = sm;                  // [K][XPAD], transposed
    float* Ws = sm + K * XPAD;       // [K][COLS]

    const int tid  = threadIdx.x;
    const int nth  = blockDim.x;
    const int row0 = blockIdx.x * BR;

    for (int i = tid; i < K * COLS / 4; i += nth)
        ((float4*)Ws)[i] = ((const float4*)W)[i];

    for (int i = tid; i < BR * (K / 4); i += nth) {
        int r  = i / (K / 4);
        int k4 = i % (K / 4);
        int row = row0 + r;
        float4 v = make_float4(0.f, 0.f, 0.f, 0.f);
        if (row < nrows) v = ((const float4*)(X + (size_t)row * K))[k4];
        Xs[(k4 * 4 + 0) * XPAD + r] = v.x;
        Xs[(k4 * 4 + 1) * XPAD + r] = v.y;
        Xs[(k4 * 4 + 2) * XPAD + r] = v.z;
        Xs[(k4 * 4 + 3) * XPAD + r] = v.w;
    }
    __syncthreads();

    const int rc = tid % 16;
    const int cc = tid / 16;

    uint64_t acc2[4][4] = {};

#pragma unroll 4
    for (int k = 0; k < K; k++) {
        float4 a4 = *(const float4*)&Xs[k * XPAD + rc * 4];
        const ulonglong2* bp = (const ulonglong2*)&Ws[k * COLS + cc * 8];
        ulonglong2 b01 = bp[0];
        ulonglong2 b23 = bp[1];
        uint64_t a0 = dup_f32(a4.x), a1 = dup_f32(a4.y);
        uint64_t a2 = dup_f32(a4.z), a3 = dup_f32(a4.w);
        fma2(acc2[0][0], a0, b01.x); fma2(acc2[0][1], a0, b01.y);
        fma2(acc2[0][2], a0, b23.x); fma2(acc2[0][3], a0, b23.y);
        fma2(acc2[1][0], a1, b01.x); fma2(acc2[1][1], a1, b01.y);
        fma2(acc2[1][2], a1, b23.x); fma2(acc2[1][3], a1, b23.y);
        fma2(acc2[2][0], a2, b01.x); fma2(acc2[2][1], a2, b01.y);
        fma2(acc2[2][2], a2, b23.x); fma2(acc2[2][3], a2, b23.y);
        fma2(acc2[3][0], a3, b01.x); fma2(acc2[3][1], a3, b01.y);
        fma2(acc2[3][2], a3, b23.x); fma2(acc2[3][3], a3, b23.y);
    }

    float al8[8], ar8[8];
#pragma unroll
    for (int j = 0; j < 8; j++) {
        al8[j] = __ldg(al + cc * 8 + j);
        ar8[j] = __ldg(ar + cc * 8 + j);
    }

    float slp[4], srp[4];
#pragma unroll
    for (int i = 0; i < 4; i++) {
        float o[8];
#pragma unroll
        for (int j2 = 0; j2 < 4; j2++) {
            float2 p = unpk(acc2[i][j2]);
            o[2 * j2] = p.x; o[2 * j2 + 1] = p.y;
        }
        int row = row0 + rc * 4 + i;
        if (row < nrows) {
            __half2 h0 = __floats2half2_rn(o[0], o[1]);
            __half2 h1 = __floats2half2_rn(o[2], o[3]);
            __half2 h2 = __floats2half2_rn(o[4], o[5]);
            __half2 h3 = __floats2half2_rn(o[6], o[7]);
            uint4 u;
            u.x = *(uint32_t*)&h0; u.y = *(uint32_t*)&h1;
            u.z = *(uint32_t*)&h2; u.w = *(uint32_t*)&h3;
            *(uint4*)(F + (size_t)row * COLS + cc * 8) = u;
        }
        float sl = 0.f, sr = 0.f;
#pragma unroll
        for (int j = 0; j < 8; j++) { sl = fmaf(o[j], al8[j], sl); sr = fmaf(o[j], ar8[j], sr); }
        slp[i] = sl; srp[i] = sr;
    }

    __syncthreads();
    float* red = sm;            // [BR][H][2]
    for (int i = tid; i < BR * H * 2; i += nth) red[i] = 0.f;
    __syncthreads();
    int h = (H == 1) ? 0 : (cc * 8) / 32;
#pragma unroll
    for (int i = 0; i < 4; i++) {
        int r = rc * 4 + i;
        atomicAdd(&red[(r * H + h) * 2 + 0], slp[i]);
        atomicAdd(&red[(r * H + h) * 2 + 1], srp[i]);
    }
    __syncthreads();
    for (int i = tid; i < BR * H; i += nth) {
        int r = i / H, hh = i % H;
        int row = row0 + r;
        if (row < nrows) {
            el[row * H + hh] = red[i * 2 + 0];
            er[row * H + hh] = red[i * 2 + 1];
        }
    }
}

// ===========================================================================
// CSR edge aggregation + fused normalize/bias/ELU. One warp per dst node.
// w = exp(leakyrelu(el[src]+er[dst])) per head (segment-max shift dropped:
// alpha = w/s invariant; scores O(1)). F payload is fp16.
// ===========================================================================
template <int H, bool ELU>
__global__ void edge_csr_kernel(const __half* __restrict__ F, const float* __restrict__ el,
                                const float* __restrict__ er, const int* __restrict__ off,
                                const int* __restrict__ esrc, const float* __restrict__ b,
                                float* __restrict__ out, int n) {
    constexpr int HD = H * 32;
    int warp = (blockIdx.x * blockDim.x + threadIdx.x) >> 5;
    int lane = threadIdx.x & 31;
    if (warp >= n) return;
    const int node = warp;

    float erh;
    if (H == 4) {
        float4 e4 = *(const float4*)(er + node * 4);
        erh = lane < 8 ? e4.x : lane < 16 ? e4.y : lane < 24 ? e4.z : e4.w;
    } else {
        erh = __ldg(er + node);
    }

    const int start = off[node], end = off[node + 1];
    float acc0 = 0.f, acc1 = 0.f, acc2 = 0.f, acc3 = 0.f, s = 0.f;

    for (int base = start; base < end; base += 32) {
        int cnt = min(32, end - base);
        int sidx = (base + lane < end) ? __ldg(esrc + base + lane) : 0;
#pragma unroll 4
        for (int j = 0; j < cnt; j++) {
            int sn = __shfl_sync(0xffffffffu, sidx, j);
            float elh;
            if (H == 4) {
                float4 e4 = *(const float4*)(el + sn * 4);
                elh = lane < 8 ? e4.x : lane < 16 ? e4.y : lane < 24 ? e4.z : e4.w;
            } else {
                elh = __ldg(el + sn);
            }
            float v = elh + erh;
            v = v > 0.f ? v : 0.2f * v;
            float w = __expf(v);
            s += w;
            if (H == 4) {
                uint2 p = *(const uint2*)(F + (size_t)sn * 128 + lane * 4);
                float2 f0 = __half22float2(*(__half2*)&p.x);
                float2 f1 = __half22float2(*(__half2*)&p.y);
                acc0 = fmaf(w, f0.x, acc0);
                acc1 = fmaf(w, f0.y, acc1);
                acc2 = fmaf(w, f1.x, acc2);
                acc3 = fmaf(w, f1.y, acc3);
            } else {
                float f = __half2float(__ldg(F + (size_t)sn * 32 + lane));
                acc0 = fmaf(w, f, acc0);
            }
        }
    }

    float inv = 1.f / fmaxf(s, 1e-9f);
    if (H == 4) {
        int c = lane * 4;
        float4 o;
        o.x = acc0 * inv + b[c + 0];
        o.y = acc1 * inv + b[c + 1];
        o.z = acc2 * inv + b[c + 2];
        o.w = acc3 * inv + b[c + 3];
        if (ELU) {
            o.x = o.x > 0.f ? o.x : expm1f(o.x);
            o.y = o.y > 0.f ? o.y : expm1f(o.y);
            o.z = o.z > 0.f ? o.z : expm1f(o.z);
            o.w = o.w > 0.f ? o.w : expm1f(o.w);
        }
        *(float4*)(out + (size_t)node * HD + c) = o;
    } else {
        float o = acc0 * inv + b[lane];
        if (ELU) o = o > 0.f ? o : expm1f(o);
        out[(size_t)node * HD + lane] = o;
    }
}

// ===========================================================================
extern "C" void kernel_launch(void* const* d_in, const int* in_sizes, int n_in,
                              void* d_out, int out_size) {
    const float* x   = (const float*)d_in[0];
    const int*   src = (const int*)d_in[1];
    const int*   dst = (const int*)d_in[2];
    const float* W1  = (const float*)d_in[3];
    const float* al1 = (const float*)d_in[4];
    const float* ar1 = (const float*)d_in[5];
    const float* b1  = (const float*)d_in[6];
    const float* W2  = (const float*)d_in[7];
    const float* al2 = (const float*)d_in[8];
    const float* ar2 = (const float*)d_in[9];
    const float* b2  = (const float*)d_in[10];
    const float* W3  = (const float*)d_in[11];
    const float* al3 = (const float*)d_in[12];
    const float* ar3 = (const float*)d_in[13];
    const float* b3  = (const float*)d_in[14];
    float* out = (float*)d_out;

    const int N = in_sizes[0] / 128;
    const int E = in_sizes[1];

    __half* fH;
    float *fB, *el, *er;
    int *deg, *off, *esrc, *bsum, *boff;
    cudaGetSymbolAddress((void**)&fH, g_fH);
    cudaGetSymbolAddress((void**)&fB, g_fB);
    cudaGetSymbolAddress((void**)&el, g_el);
    cudaGetSymbolAddress((void**)&er, g_er);
    cudaGetSymbolAddress((void**)&deg, g_deg);
    cudaGetSymbolAddress((void**)&off, g_off);
    cudaGetSymbolAddress((void**)&esrc, g_esrc);
    cudaGetSymbolAddress((void**)&bsum, g_bsum);
    cudaGetSymbolAddress((void**)&boff, g_boff);

    const int SMEM128 = (128 * 68 + 128 * 128) * (int)sizeof(float);
    const int SMEM32  = (128 * 68 + 128 * 32)  * (int)sizeof(float);
    cudaFuncSetAttribute((const void*)gemm_attn_kernel<128, 4>,
                         cudaFuncAttributeMaxDynamicSharedMemorySize, SMEM128);
    cudaFuncSetAttribute((const void*)gemm_attn_kernel<32, 1>,
                         cudaFuncAttributeMaxDynamicSharedMemorySize, SMEM32);

    const int gemm_blocks = (N + 63) / 64;
    const int eblk = (E + 255) / 256;
    const int nb   = (N + 1023) / 1024;
    const int edge_blocks = (N * 32 + 255) / 256;

    // ---------------- CSR build (reused by all 3 layers) ----------------
    cudaMemsetAsync(deg, 0, (size_t)N * sizeof(int));
    hist_kernel<<<eblk, 256>>>(dst, deg, E);
    bsum_kernel<<<nb, 256>>>(deg, bsum, N);
    bscan_kernel<<<1, 128>>>(bsum, boff, off, nb, N);
    scan_chunk_kernel<<<nb, 256>>>(deg, boff, off, N);
    cudaMemsetAsync(deg, 0, (size_t)N * sizeof(int));
    scatter_kernel<<<eblk, 256>>>(src, dst, off, deg, esrc, E);

    // ---------------- Layer 1 ----------------
    gemm_attn_kernel<128, 4><<<gemm_blocks, 256, SMEM128>>>(
        x, W1, al1, ar1, fH, el, er, N);
    edge_csr_kernel<4, true><<<edge_blocks, 256>>>(fH, el, er, off, esrc, b1, fB, N);

    // ---------------- Layer 2 ----------------
    gemm_attn_kernel<128, 4><<<gemm_blocks, 256, SMEM128>>>(
        fB, W2, al2, ar2, fH, el, er, N);
    edge_csr_kernel<4, true><<<edge_blocks, 256>>>(fH, el, er, off, esrc, b2, fB, N);

    // ---------------- Layer 3 ----------------
    gemm_attn_kernel<32, 1><<<gemm_blocks, 64, SMEM32>>>(
        fB, W3, al3, ar3, fH, el, er, N);
    edge_csr_kernel<1, false><<<edge_blocks, 256>>>(fH, el, er, off, esrc, b3, out, N);
}